// round 2
// baseline (speedup 1.0000x reference)
#include <cuda_runtime.h>
#include <math.h>

#define H 64
#define W 64
#define C 256
#define P 7
#define NUM_ROIS 256

__device__ __forceinline__ float4 fmax4(float4 a, float4 b) {
    a.x = fmaxf(a.x, b.x);
    a.y = fmaxf(a.y, b.y);
    a.z = fmaxf(a.z, b.z);
    a.w = fmaxf(a.w, b.w);
    return a;
}

// One block per (roi, i) — 256 threads.
//   tid >> 6  : j-quadrant (0..3), loops j = jq, jq+4
//   tid & 63  : float4 channel group (c = (tid&63)*4)
__global__ __launch_bounds__(256) void roi_pool_kernel(
    const float* __restrict__ feat,   // (H, W, C)
    const float* __restrict__ rois,   // (NUM_ROIS, 4) = x1,y1,x2,y2
    float* __restrict__ out)          // (NUM_ROIS, P, P, C)
{
    const int b = blockIdx.x;
    const int r = b / P;
    const int i = b % P;

    const float x1 = rois[r * 4 + 0];
    const float y1 = rois[r * 4 + 1];
    const float x2 = rois[r * 4 + 2];
    const float y2 = rois[r * 4 + 3];

    // x axis (H) bin for this block's i — exact reference math
    const int lox = (int)floorf(x1 * (float)H);
    const int hix = (int)ceilf(x2 * (float)H);
    const int spanx = max(hix - lox, 1);
    int xs = lox + (i * spanx) / P;                       // floor div (nonneg)
    const int xe = lox + ((i + 1) * spanx + (P - 1)) / P; // ceil div
    const int xlen = max(xe - xs, 1);                     // from UNCLIPPED start
    xs = min(max(xs, 0), H - 1);

    // y axis (W) span (per-j bounds inside loop)
    const int loy = (int)floorf(y1 * (float)W);
    const int hiy = (int)ceilf(y2 * (float)W);
    const int spany = max(hiy - loy, 1);

    const int jq = threadIdx.x >> 6;          // 0..3
    const int c4 = (threadIdx.x & 63) << 2;   // channel offset (float4)

    const float NEG = -INFINITY;

    for (int j = jq; j < P; j += 4) {
        int ys = loy + (j * spany) / P;
        const int ye = loy + ((j + 1) * spany + (P - 1)) / P;
        const int ylen = max(ye - ys, 1);
        ys = min(max(ys, 0), W - 1);

        float4 acc = make_float4(NEG, NEG, NEG, NEG);

        for (int sx = 0; sx < xlen; ++sx) {
            const int x = min(xs + sx, H - 1);
            const float* rowp = feat + (size_t)x * (W * C) + c4;
            for (int sy = 0; sy < ylen; ++sy) {
                const int y = min(ys + sy, W - 1);
                float4 v = *reinterpret_cast<const float4*>(rowp + y * C);
                acc = fmax4(acc, v);
            }
        }

        float* op = out + (((size_t)(r * P + i) * P + j) * C) + c4;
        *reinterpret_cast<float4*>(op) = acc;
    }
}

extern "C" void kernel_launch(void* const* d_in, const int* in_sizes, int n_in,
                              void* d_out, int out_size) {
    const float* feat = (const float*)d_in[0];
    const float* rois = (const float*)d_in[1];
    // Defensive: metadata order should be featMap (1048576), rois (1024).
    if (n_in >= 2 && in_sizes[0] == NUM_ROIS * 4 && in_sizes[1] == H * W * C) {
        feat = (const float*)d_in[1];
        rois = (const float*)d_in[0];
    }
    float* out = (float*)d_out;

    roi_pool_kernel<<<NUM_ROIS * P, 256>>>(feat, rois, out);
}